// round 1
// baseline (speedup 1.0000x reference)
#include <cuda_runtime.h>

// Caps_Layer: B=128, N=512, D=300, NUM_CAPSULE=10, DIM_CAPSULE=64, ROUTINGS=5
// Algorithm: u = x@W is NEVER materialized. Per routing iteration, per batch b:
//   c = softmax_i(b)                              [10,512]
//   y[i,d]  = sum_j c[i,j] * x[b,j,d]             [10,300]
//   o_raw[i,k] = sum_d y[i,d] * W[d, i*64+k]      [10,64]
//   o = o_raw / sqrt(|o_raw|^2 + 1e-7)            (squash)
//   v[i,d]  = sum_k o[i,k] * W[d, i*64+k]         [10,300]
//   b[i,j]  = sum_d x[b,j,d] * v[i,d]             [10,512]
// One CTA per batch; all small state in shared memory; x streamed from L2.

#define BB   128
#define NN   512
#define DD   300
#define NC   10
#define DC   64
#define MM   640      // NC*DC
#define ROUTS 5
#define NT   640      // threads per CTA (== NC*DC)

__global__ __launch_bounds__(NT, 1)
void caps_kernel(const float* __restrict__ x,
                 const float* __restrict__ W,
                 float* __restrict__ out)
{
    __shared__ __align__(16) float c_s[NC * NN];   // holds b, then c (in place)
    __shared__ __align__(16) float y_s[NC * DD];
    __shared__ __align__(16) float v_s[NC * DD];   // also y-reduction scratch
    __shared__ __align__(16) float o_s[NC * DC];
    __shared__ float nrm[NC];

    const int b   = blockIdx.x;
    const int tid = threadIdx.x;
    const float* __restrict__ xb = x + (size_t)b * NN * DD;

    // b <- 0
    for (int idx = tid; idx < NC * NN; idx += NT) c_s[idx] = 0.0f;
    __syncthreads();

    for (int it = 0; it < ROUTS; ++it) {
        // ---- softmax over capsules i, per j (b -> c in place) ----
        if (tid < NN) {
            const int j = tid;
            float bv[NC];
            float mx = -1e30f;
            #pragma unroll
            for (int i = 0; i < NC; ++i) { bv[i] = c_s[i * NN + j]; mx = fmaxf(mx, bv[i]); }
            float s = 0.0f;
            #pragma unroll
            for (int i = 0; i < NC; ++i) { bv[i] = __expf(bv[i] - mx); s += bv[i]; }
            const float inv = 1.0f / s;
            #pragma unroll
            for (int i = 0; i < NC; ++i) c_s[i * NN + j] = bv[i] * inv;
        }
        __syncthreads();

        // ---- P1: y[i,d] = sum_j c[i,j] * x[j,d]  (two j-halves, then reduce) ----
        {
            const int g = tid / 320;          // j-group 0/1
            const int d = tid - g * 320;      // 0..319, active if < 300
            float acc[NC];
            #pragma unroll
            for (int i = 0; i < NC; ++i) acc[i] = 0.0f;

            if (d < DD) {
                const int j0 = g * 256;
                const float* __restrict__ xp = xb + (size_t)j0 * DD + d;
                for (int jc = 0; jc < 256; jc += 4) {
                    const float xv0 = xp[(jc + 0) * DD];
                    const float xv1 = xp[(jc + 1) * DD];
                    const float xv2 = xp[(jc + 2) * DD];
                    const float xv3 = xp[(jc + 3) * DD];
                    #pragma unroll
                    for (int i = 0; i < NC; ++i) {
                        const float4 c4 = *reinterpret_cast<const float4*>(&c_s[i * NN + j0 + jc]);
                        acc[i] += c4.x * xv0 + c4.y * xv1 + c4.z * xv2 + c4.w * xv3;
                    }
                }
                if (g == 1) {
                    #pragma unroll
                    for (int i = 0; i < NC; ++i) v_s[i * DD + d] = acc[i];
                }
            }
            __syncthreads();
            if (d < DD && g == 0) {
                #pragma unroll
                for (int i = 0; i < NC; ++i) y_s[i * DD + d] = acc[i] + v_s[i * DD + d];
            }
        }
        __syncthreads();

        // ---- P2: o_raw[i,k] = sum_d y[i,d] * W[d, i*64+k] ----
        {
            const int ci = tid >> 6;   // capsule
            const float* __restrict__ Wp = W + (tid & 63) + ci * DC;
            const float* __restrict__ yp = y_s + ci * DD;
            float a0 = 0.f, a1 = 0.f, a2 = 0.f, a3 = 0.f;
            for (int d = 0; d < DD; d += 4) {
                a0 += yp[d + 0] * Wp[(size_t)(d + 0) * MM];
                a1 += yp[d + 1] * Wp[(size_t)(d + 1) * MM];
                a2 += yp[d + 2] * Wp[(size_t)(d + 2) * MM];
                a3 += yp[d + 3] * Wp[(size_t)(d + 3) * MM];
            }
            o_s[tid] = (a0 + a1) + (a2 + a3);
        }
        __syncthreads();

        // ---- squash norms ----
        if (tid < NC) {
            float s = 1e-7f;
            #pragma unroll
            for (int k = 0; k < DC; ++k) { const float v = o_s[tid * DC + k]; s += v * v; }
            nrm[tid] = rsqrtf(s);
        }
        __syncthreads();
        {
            const int ci = tid >> 6;
            const float o = o_s[tid] * nrm[ci];
            o_s[tid] = o;
            if (it == ROUTS - 1) out[(size_t)b * MM + tid] = o;
        }
        if (it == ROUTS - 1) break;   // uniform across all threads
        __syncthreads();

        // ---- P3: v[i,d] = sum_k o[i,k] * W[d, i*64+k] ----
        for (int t = tid; t < NC * DD; t += NT) {
            const int i = t / DD;
            const int d = t - i * DD;
            const float* __restrict__ Wr = W + (size_t)d * MM + i * DC;
            const float* __restrict__ op = o_s + i * DC;
            float acc = 0.0f;
            #pragma unroll
            for (int k = 0; k < DC; k += 4) {
                const float4 w4 = *reinterpret_cast<const float4*>(Wr + k);
                acc += op[k + 0] * w4.x + op[k + 1] * w4.y
                     + op[k + 2] * w4.z + op[k + 3] * w4.w;
            }
            v_s[i * DD + d] = acc;
        }
        __syncthreads();

        // ---- P4: b[i,j] = sum_d x[j,d] * v[i,d] ----
        if (tid < NN) {
            const float* __restrict__ xp = xb + (size_t)tid * DD;
            float acc[NC];
            #pragma unroll
            for (int i = 0; i < NC; ++i) acc[i] = 0.0f;
            for (int d = 0; d < DD; d += 4) {
                const float4 xv = *reinterpret_cast<const float4*>(xp + d);
                #pragma unroll
                for (int i = 0; i < NC; ++i) {
                    const float4 v4 = *reinterpret_cast<const float4*>(&v_s[i * DD + d]);
                    acc[i] += xv.x * v4.x + xv.y * v4.y + xv.z * v4.z + xv.w * v4.w;
                }
            }
            #pragma unroll
            for (int i = 0; i < NC; ++i) c_s[i * NN + tid] = acc[i];
        }
        __syncthreads();
    }
}

extern "C" void kernel_launch(void* const* d_in, const int* in_sizes, int n_in,
                              void* d_out, int out_size)
{
    // metadata order: x [128,512,300] f32, W [1,300,640] f32 (defensive swap by size)
    const float* x = (const float*)d_in[0];
    const float* W = (const float*)d_in[1];
    if (n_in >= 2 && in_sizes[0] < in_sizes[1]) {
        x = (const float*)d_in[1];
        W = (const float*)d_in[0];
    }
    float* out = (float*)d_out;
    caps_kernel<<<BB, NT>>>(x, W, out);
}

// round 2
// speedup vs baseline: 1.1998x; 1.1998x over previous
#include <cuda_runtime.h>

// Caps_Layer: B=128, N=512, D=300, NUM_CAPSULE=10, DIM_CAPSULE=64, ROUTINGS=5
// u = x@W never materialized. Per iteration:
//   P3: v[i,d] = sum_k o[i,k] W[d,i*64+k]        (smem-staged W tiles, coalesced)
//   XPASS (tiled over j, x staged in smem via cp.async):
//       b[i,j] = sum_d x[j,d] v[i,d] ; c = softmax_i(b) ; y[i,d] += c[i,j] x[j,d]
//   P2: o_raw[i,k] = sum_d y[i,d] W[d,i*64+k]    (coalesced LDG)
//   squash -> o
// Iteration 0: c uniform -> y[i,:] = 0.1 * colsum(x).

#define BB   128
#define NN   512
#define DD   300
#define NC   10
#define DC   64
#define MM   640
#define NT   640
#define TJ   32          // j-tile
#define NTILE (NN/TJ)    // 16
#define TD   30          // d-tile for P3 W staging
#define WPAD 644         // padded W row (floats) in smem
#define NBW  15          // warps doing B phase

// ---- shared memory layout (floats) ----
#define OFF_ARENA 0          // 19328: xs[2][9600] or Wt[30*644=19320]
#define OFF_V     19328      // 3000
#define OFF_YP    22328      // 6000 (ypart[2][10][300])
#define OFF_Y     28328      // 3000
#define OFF_O     31328      // 640
#define OFF_NRM   31968      // 16
#define OFF_BPART 31984      // 4800 (15*10*32)  (also it0 colsum scratch 600)
#define OFF_BROW  36784      // 320
#define OFF_C2T   37104      // 640 floats = 320 u64 (splatted c)
#define SMEM_FLOATS 37744
#define SMEM_BYTES (SMEM_FLOATS*4)

typedef unsigned long long u64;
struct u64x2 { u64 x, y; };

__device__ __forceinline__ void fma2(u64& acc, u64 a, u64 b) {
    asm("fma.rn.f32x2 %0, %1, %2, %0;" : "+l"(acc) : "l"(a), "l"(b));
}
__device__ __forceinline__ u64 add2(u64 a, u64 b) {
    u64 r; asm("add.rn.f32x2 %0, %1, %2;" : "=l"(r) : "l"(a), "l"(b)); return r;
}
__device__ __forceinline__ float fold2(u64 v) {
    float lo, hi; asm("mov.b64 {%0,%1}, %2;" : "=f"(lo), "=f"(hi) : "l"(v)); return lo + hi;
}
__device__ __forceinline__ u64 splat2(float f) {
    u64 r; asm("mov.b64 %0, {%1,%1};" : "=l"(r) : "f"(f)); return r;
}
__device__ __forceinline__ void cp16(void* smem_dst, const void* gsrc) {
    unsigned sa = (unsigned)__cvta_generic_to_shared(smem_dst);
    asm volatile("cp.async.cg.shared.global [%0], [%1], 16;" :: "r"(sa), "l"(gsrc));
}
__device__ __forceinline__ void cp_commit() { asm volatile("cp.async.commit_group;"); }
template <int N> __device__ __forceinline__ void cp_wait() {
    asm volatile("cp.async.wait_group %0;" :: "n"(N));
}

__global__ __launch_bounds__(NT, 1)
void caps_kernel(const float* __restrict__ x,
                 const float* __restrict__ W,
                 float* __restrict__ out)
{
    extern __shared__ float sm[];
    const int b   = blockIdx.x;
    const int t   = threadIdx.x;
    const float* __restrict__ xb = x + (size_t)b * NN * DD;

    float* v_s   = sm + OFF_V;
    float* yp_s  = sm + OFF_YP;
    float* y_s   = sm + OFF_Y;
    float* o_s   = sm + OFF_O;
    float* nrm   = sm + OFF_NRM;
    float* bpart = sm + OFF_BPART;
    float* brow  = sm + OFF_BROW;
    u64*   c2t   = (u64*)(sm + OFF_C2T);

    // ================= iteration 0: y[i,d] = 0.1 * colsum_d =================
    if (t < 600) {
        const int g = t / 300, d = t - g * 300;
        const float* __restrict__ xp = xb + (size_t)(g * 256) * DD + d;
        float a0 = 0.f, a1 = 0.f, a2 = 0.f, a3 = 0.f;
        for (int j = 0; j < 256; j += 4) {
            a0 += xp[(j + 0) * DD]; a1 += xp[(j + 1) * DD];
            a2 += xp[(j + 2) * DD]; a3 += xp[(j + 3) * DD];
        }
        bpart[g * 300 + d] = (a0 + a1) + (a2 + a3);
    }
    __syncthreads();
    for (int idx = t; idx < NC * DD; idx += NT) {
        const int d = idx % DD;
        y_s[idx] = 0.1f * (bpart[d] + bpart[300 + d]);
    }
    __syncthreads();

    for (int r = 0; r < 5; ++r) {
        // ---------------- P2: o_raw[i,k] = sum_d y[i,d] W[d,m], m=t ----------------
        {
            const int i = t >> 6;
            const float* __restrict__ Wp = W + t;
            const float* __restrict__ yp = y_s + i * DD;
            float a0 = 0.f, a1 = 0.f, a2 = 0.f, a3 = 0.f;
            for (int d = 0; d < DD; d += 4) {
                const float4 y4 = *reinterpret_cast<const float4*>(yp + d);
                a0 += y4.x * Wp[(size_t)(d + 0) * MM];
                a1 += y4.y * Wp[(size_t)(d + 1) * MM];
                a2 += y4.z * Wp[(size_t)(d + 2) * MM];
                a3 += y4.w * Wp[(size_t)(d + 3) * MM];
            }
            o_s[t] = (a0 + a1) + (a2 + a3);
        }
        __syncthreads();
        if (t < NC) {
            float s = 1e-7f;
            #pragma unroll
            for (int k = 0; k < DC; ++k) { const float v = o_s[t * DC + k]; s += v * v; }
            nrm[t] = rsqrtf(s);
        }
        __syncthreads();
        o_s[t] *= nrm[t >> 6];
        __syncthreads();
        if (r == 4) break;

        // ---------------- P3: v[i,d] = sum_k o[i,k] W[d, i*64+k] ----------------
        {
            float* Wt = sm + OFF_ARENA;
            for (int tile = 0; tile < 10; ++tile) {
                const int d0 = tile * TD;
                // load W[d0:d0+30, :] coalesced, rows padded to WPAD
                for (int idx = t; idx < TD * (MM / 4); idx += NT) {
                    const int dt = idx / (MM / 4);
                    const int m4 = idx - dt * (MM / 4);
                    const float4 w4 = *reinterpret_cast<const float4*>(
                        W + (size_t)(d0 + dt) * MM + m4 * 4);
                    *reinterpret_cast<float4*>(Wt + dt * WPAD + m4 * 4) = w4;
                }
                __syncthreads();
                if (t < NC * TD) {
                    const int i = t / TD, dd = t - i * TD;
                    u64 a01 = 0ull, a23 = 0ull;
                    #pragma unroll
                    for (int k4 = 0; k4 < 16; ++k4) {
                        const u64x2 w = *reinterpret_cast<const u64x2*>(
                            Wt + dd * WPAD + i * DC + k4 * 4);
                        const u64x2 oo = *reinterpret_cast<const u64x2*>(
                            o_s + i * DC + k4 * 4);
                        fma2(a01, w.x, oo.x); fma2(a23, w.y, oo.y);
                    }
                    v_s[i * DD + d0 + dd] = fold2(a01) + fold2(a23);
                }
                __syncthreads();
            }
        }

        // ---------------- XPASS: b -> softmax -> c -> y (tiled, cp.async) ----------------
        {
            // prologue: issue tile 0
            for (int idx = t; idx < TJ * DD / 4; idx += NT)
                cp16(sm + OFF_ARENA + idx * 4, xb + idx * 4);
            cp_commit();
            for (int idx = t; idx < 2 * NC * DD; idx += NT) yp_s[idx] = 0.f;

            for (int tile = 0; tile < NTILE; ++tile) {
                if (tile < NTILE - 1) {
                    const int nb = (tile + 1) & 1;
                    const float* gsrc = xb + (size_t)(tile + 1) * TJ * DD;
                    for (int idx = t; idx < TJ * DD / 4; idx += NT)
                        cp16(sm + OFF_ARENA + nb * (TJ * DD) + idx * 4, gsrc + idx * 4);
                    cp_commit();
                    cp_wait<1>();
                } else {
                    cp_wait<0>();
                }
                __syncthreads();
                const float* xs = sm + OFF_ARENA + (tile & 1) * (TJ * DD);

                // B: partial b, 15 warps, lanes = j
                if (t < NBW * 32) {
                    const int w = t >> 5, lane = t & 31;
                    u64 acc[NC];
                    #pragma unroll
                    for (int i = 0; i < NC; ++i) acc[i] = 0ull;
                    #pragma unroll
                    for (int s = 0; s < 5; ++s) {
                        const int d4 = w + NBW * s;
                        const u64x2 xv = *reinterpret_cast<const u64x2*>(
                            xs + lane * DD + d4 * 4);
                        #pragma unroll
                        for (int i = 0; i < NC; ++i) {
                            const u64x2 vv = *reinterpret_cast<const u64x2*>(
                                v_s + i * DD + d4 * 4);
                            fma2(acc[i], xv.x, vv.x); fma2(acc[i], xv.y, vv.y);
                        }
                    }
                    #pragma unroll
                    for (int i = 0; i < NC; ++i)
                        bpart[w * 320 + i * 32 + lane] = fold2(acc[i]);
                }
                __syncthreads();
                // reduce partials
                if (t < NC * 32) {
                    const int i = t >> 5, j = t & 31;
                    float s = 0.f;
                    #pragma unroll
                    for (int w = 0; w < NBW; ++w) s += bpart[w * 320 + i * 32 + j];
                    brow[i * 32 + j] = s;
                }
                __syncthreads();
                // softmax per j, store splatted c
                if (t < 32) {
                    const int j = t;
                    float bv[NC], mx = -1e30f;
                    #pragma unroll
                    for (int i = 0; i < NC; ++i) { bv[i] = brow[i * 32 + j]; mx = fmaxf(mx, bv[i]); }
                    float s = 0.f;
                    #pragma unroll
                    for (int i = 0; i < NC; ++i) { bv[i] = __expf(bv[i] - mx); s += bv[i]; }
                    const float inv = 1.0f / s;
                    #pragma unroll
                    for (int i = 0; i < NC; ++i) c2t[j * NC + i] = splat2(bv[i] * inv);
                }
                __syncthreads();
                // C: y[i,d] += c[i,j] * x[j,d]   (d-pairs x 2 j-groups)
                if (t < 300) {
                    const int dp = t % 150, jg = t / 150;
                    const int d0 = dp * 2, j0 = jg * 16;
                    u64 acc[NC];
                    #pragma unroll
                    for (int i = 0; i < NC; ++i) acc[i] = 0ull;
                    #pragma unroll
                    for (int jj = 0; jj < 16; ++jj) {
                        const int j = j0 + jj;
                        const u64 xv = *reinterpret_cast<const u64*>(xs + j * DD + d0);
                        #pragma unroll
                        for (int p = 0; p < 5; ++p) {
                            const u64x2 cc = *reinterpret_cast<const u64x2*>(
                                &c2t[j * NC + 2 * p]);
                            fma2(acc[2 * p], xv, cc.x); fma2(acc[2 * p + 1], xv, cc.y);
                        }
                    }
                    #pragma unroll
                    for (int i = 0; i < NC; ++i) {
                        u64* yp = reinterpret_cast<u64*>(yp_s + jg * (NC * DD) + i * DD + d0);
                        *yp = add2(*yp, acc[i]);
                    }
                }
                __syncthreads();
            }
            // y = sum of both j-group partials
            for (int idx = t; idx < NC * DD; idx += NT)
                y_s[idx] = yp_s[idx] + yp_s[NC * DD + idx];
            __syncthreads();
        }
    }

    out[(size_t)b * MM + t] = o_s[t];
}

extern "C" void kernel_launch(void* const* d_in, const int* in_sizes, int n_in,
                              void* d_out, int out_size)
{
    const float* x = (const float*)d_in[0];
    const float* W = (const float*)d_in[1];
    if (n_in >= 2 && in_sizes[0] < in_sizes[1]) {
        x = (const float*)d_in[1];
        W = (const float*)d_in[0];
    }
    float* out = (float*)d_out;
    cudaFuncSetAttribute(caps_kernel, cudaFuncAttributeMaxDynamicSharedMemorySize, SMEM_BYTES);
    caps_kernel<<<BB, NT, SMEM_BYTES>>>(x, W, out);
}

// round 3
// speedup vs baseline: 1.3401x; 1.1169x over previous
#include <cuda_runtime.h>

// Caps_Layer: B=128, N=512, D=300, NUM_CAPSULE=10, DIM_CAPSULE=64, ROUTINGS=5
// u = x@W never materialized. W additionally pre-transposed (prologue kernel)
// into Wt[m][d] so P3 gets coalesced loads. Per iteration:
//   P2: o_raw[m] = sum_d y[i(m),d] W[d,m]     (float4 W, f32x2, 4-way d-split)
//   squash -> o  (warp-shuffle norms)
//   P3: v[i,d] = sum_k o[i,k] Wt[i*64+k, d]   (coalesced LDG.64 + f32x2)
//   XPASS tiled over j (32/tile, double-buffered cp.async):
//       b[i,j] = x[j,:]·v[i,:]  (20 warps, d-split)
//       c = softmax_i(b)        (512 thr, shfl-16)
//       yacc[i,d] += c[i,j] x[j,d]  (register accumulators across tiles)
// Iteration 0: c uniform -> y = 0.1 * colsum(x).

#define BB   128
#define NN   512
#define DD   300
#define NC   10
#define DC   64
#define MM   640
#define NT   640
#define TJ   32
#define NTILE (NN/TJ)

// shared memory layout (float indices)
#define OFF_ARENA 0        // 2 x 9600 (x tiles)
#define OFF_V     19200    // 3000
#define OFF_Y     22200    // 3000
#define OFF_YP    25200    // 12000
#define OFF_O     37200    // 640
#define OFF_NRM   37840    // 16
#define OFF_BPART 37856    // 20*352 = 7040 (also P2 partials 4*640, it0 600)
#define OFF_C     44896    // 32*12 = 384
#define SMEM_FLOATS 45280
#define SMEM_BYTES (SMEM_FLOATS*4)

typedef unsigned long long u64;
struct u64x2 { u64 x, y; };

__device__ float Wt_g[MM * DD];   // W transposed: Wt[m*300 + d]

__device__ __forceinline__ void fma2(u64& acc, u64 a, u64 b) {
    asm("fma.rn.f32x2 %0, %1, %2, %0;" : "+l"(acc) : "l"(a), "l"(b));
}
__device__ __forceinline__ u64 splat2(float f) {
    u64 r; asm("mov.b64 %0, {%1,%1};" : "=l"(r) : "f"(f)); return r;
}
__device__ __forceinline__ void cp16(void* smem_dst, const void* gsrc) {
    unsigned sa = (unsigned)__cvta_generic_to_shared(smem_dst);
    asm volatile("cp.async.cg.shared.global [%0], [%1], 16;" :: "r"(sa), "l"(gsrc));
}
__device__ __forceinline__ void cp_commit() { asm volatile("cp.async.commit_group;"); }
template <int N> __device__ __forceinline__ void cp_wait() {
    asm volatile("cp.async.wait_group %0;" :: "n"(N));
}

// ---------------- prologue: W[300][640] -> Wt[640][300] ----------------
__global__ void transpose_W(const float* __restrict__ W)
{
    __shared__ float tl[32][33];
    const int tx = threadIdx.x, ty = threadIdx.y;     // 32 x 8
    const int m0 = blockIdx.x * 32, d0 = blockIdx.y * 32;
    #pragma unroll
    for (int k = 0; k < 4; ++k) {
        const int d = d0 + ty + k * 8;
        if (d < DD) tl[ty + k * 8][tx] = W[(size_t)d * MM + m0 + tx];
    }
    __syncthreads();
    #pragma unroll
    for (int k = 0; k < 4; ++k) {
        const int m = m0 + ty + k * 8;
        const int d = d0 + tx;
        if (d < DD) Wt_g[(size_t)m * DD + d] = tl[tx][ty + k * 8];
    }
}

__global__ __launch_bounds__(NT, 1)
void caps_kernel(const float* __restrict__ x,
                 const float* __restrict__ W,
                 float* __restrict__ out)
{
    extern __shared__ float sm[];
    const int b    = blockIdx.x;
    const int t    = threadIdx.x;
    const int w    = t >> 5;
    const int lane = t & 31;
    const float* __restrict__ xb = x + (size_t)b * NN * DD;

    float* v_s   = sm + OFF_V;
    float* y_s   = sm + OFF_Y;
    float* yp_s  = sm + OFF_YP;
    float* o_s   = sm + OFF_O;
    float* nrm   = sm + OFF_NRM;
    float* bpart = sm + OFF_BPART;
    float* c_s   = sm + OFF_C;

    // ---- iteration 0: y[i,d] = 0.1 * colsum_d(x) ----
    if (t < 600) {
        const int g = t / 300, d = t - g * 300;
        const float* __restrict__ xp = xb + (size_t)(g * 256) * DD + d;
        float a0 = 0.f, a1 = 0.f, a2 = 0.f, a3 = 0.f;
        for (int j = 0; j < 256; j += 4) {
            a0 += xp[(j + 0) * DD]; a1 += xp[(j + 1) * DD];
            a2 += xp[(j + 2) * DD]; a3 += xp[(j + 3) * DD];
        }
        bpart[g * 300 + d] = (a0 + a1) + (a2 + a3);
    }
    __syncthreads();
    for (int idx = t; idx < NC * DD; idx += NT) {
        const int d = idx % DD;
        y_s[idx] = 0.1f * (bpart[d] + bpart[300 + d]);
    }
    __syncthreads();

    for (int r = 0; r < 5; ++r) {
        // ---------------- P2: o_raw[m] = sum_d y[i,d] W[d,m] ----------------
        {
            const int ds  = t / 160;            // d-slice 0..3
            const int m4  = (t - ds * 160) * 4; // 4 consecutive m
            const int ci  = m4 >> 6;
            const int d0  = ds * 75;
            const float* __restrict__ yp = y_s + ci * DD;
            u64 a01 = 0ull, a23 = 0ull;
            #pragma unroll 5
            for (int d = d0; d < d0 + 75; ++d) {
                const u64x2 w4 = *reinterpret_cast<const u64x2*>(W + (size_t)d * MM + m4);
                const u64 ys = splat2(yp[d]);
                fma2(a01, w4.x, ys); fma2(a23, w4.y, ys);
            }
            *reinterpret_cast<u64*>(bpart + ds * MM + m4)     = a01;
            *reinterpret_cast<u64*>(bpart + ds * MM + m4 + 2) = a23;
        }
        __syncthreads();
        o_s[t] = bpart[t] + bpart[MM + t] + bpart[2 * MM + t] + bpart[3 * MM + t];
        __syncthreads();
        // squash norms: 10 warps, shuffle reduce
        if (t < 320) {
            const int i = t >> 5;
            const float v0 = o_s[i * DC + lane];
            const float v1 = o_s[i * DC + 32 + lane];
            float s = v0 * v0 + v1 * v1;
            #pragma unroll
            for (int k = 16; k > 0; k >>= 1) s += __shfl_xor_sync(0xffffffffu, s, k);
            if (lane == 0) nrm[i] = rsqrtf(s + 1e-7f);
        }
        __syncthreads();
        const float ov = o_s[t] * nrm[t >> 6];
        o_s[t] = ov;
        if (r == 4) { out[(size_t)b * MM + t] = ov; break; }
        __syncthreads();

        // ---------------- P3: v[i,d] = sum_k o[i,k] Wt[i*64+k, d] ----------------
        for (int idx = t; idx < NC * 150; idx += NT) {
            const int i  = idx / 150;
            const int d0 = (idx - i * 150) * 2;
            const float* __restrict__ ob = o_s + i * DC;
            const float* __restrict__ wt = Wt_g + (size_t)i * DC * DD + d0;
            u64 acc = 0ull;
            #pragma unroll 8
            for (int k = 0; k < DC; ++k)
                fma2(acc, *reinterpret_cast<const u64*>(wt + (size_t)k * DD), splat2(ob[k]));
            *reinterpret_cast<u64*>(v_s + i * DD + d0) = acc;
        }
        __syncthreads();

        // ---------------- XPASS ----------------
        // per-thread y accumulators (t<600): thread = (jg, d-pair)
        u64 yacc[NC];
        #pragma unroll
        for (int i = 0; i < NC; ++i) yacc[i] = 0ull;
        const int jg = t / 150;
        const int d0c = (t - jg * 150) * 2;

        // prologue: tile 0
        for (int idx = t; idx < TJ * DD / 4; idx += NT)
            cp16(sm + OFF_ARENA + idx * 4, xb + idx * 4);
        cp_commit();

        for (int tile = 0; tile < NTILE; ++tile) {
            if (tile < NTILE - 1) {
                const int nb = (tile + 1) & 1;
                const float* gsrc = xb + (size_t)(tile + 1) * TJ * DD;
                for (int idx = t; idx < TJ * DD / 4; idx += NT)
                    cp16(sm + OFF_ARENA + nb * (TJ * DD) + idx * 4, gsrc + idx * 4);
                cp_commit();
                cp_wait<1>();
            } else {
                cp_wait<0>();
            }
            __syncthreads();
            const float* xs = sm + OFF_ARENA + (tile & 1) * (TJ * DD);

            // B: b[i,j] partials, 20 warps d-split (15 warps x 16d, 5 warps x 12d)
            {
                int d0, ns;
                if (w < 15) { d0 = w * 16; ns = 4; }
                else        { d0 = 240 + (w - 15) * 12; ns = 3; }
                float acc[NC];
                #pragma unroll
                for (int i = 0; i < NC; ++i) acc[i] = 0.f;
                for (int s = 0; s < ns; ++s) {
                    const int db = d0 + 4 * s;
                    const float4 xv = *reinterpret_cast<const float4*>(xs + lane * DD + db);
                    #pragma unroll
                    for (int i = 0; i < NC; ++i) {
                        const float4 vv = *reinterpret_cast<const float4*>(v_s + i * DD + db);
                        acc[i] += xv.x * vv.x + xv.y * vv.y + xv.z * vv.z + xv.w * vv.w;
                    }
                }
                #pragma unroll
                for (int i = 0; i < NC; ++i)
                    bpart[w * 352 + lane * 11 + i] = acc[i];
            }
            __syncthreads();

            // softmax over i, per j: 512 threads, shfl within 16-lane groups
            if (t < 512) {
                const int j = t >> 4, ii = t & 15;
                float s;
                if (ii < NC) {
                    s = 0.f;
                    #pragma unroll
                    for (int ww = 0; ww < 20; ++ww) s += bpart[ww * 352 + j * 11 + ii];
                } else s = -1e30f;
                float m = s;
                #pragma unroll
                for (int k = 8; k > 0; k >>= 1) m = fmaxf(m, __shfl_xor_sync(0xffffffffu, m, k, 16));
                const float e = __expf(s - m);
                float sum = e;
                #pragma unroll
                for (int k = 8; k > 0; k >>= 1) sum += __shfl_xor_sync(0xffffffffu, sum, k, 16);
                if (ii < NC) c_s[j * 12 + ii] = e * (1.0f / sum);
            }
            __syncthreads();

            // C: yacc[i] += c[i,j] * x[j, d0c..d0c+1]  (register accumulation)
            if (t < 600) {
                const int j0 = jg * 8;
                #pragma unroll
                for (int jj = 0; jj < 8; ++jj) {
                    const int j = j0 + jj;
                    const u64 xv = *reinterpret_cast<const u64*>(xs + j * DD + d0c);
                    const float4 c0 = *reinterpret_cast<const float4*>(c_s + j * 12);
                    const float4 c1 = *reinterpret_cast<const float4*>(c_s + j * 12 + 4);
                    const float2 c2 = *reinterpret_cast<const float2*>(c_s + j * 12 + 8);
                    fma2(yacc[0], xv, splat2(c0.x));
                    fma2(yacc[1], xv, splat2(c0.y));
                    fma2(yacc[2], xv, splat2(c0.z));
                    fma2(yacc[3], xv, splat2(c0.w));
                    fma2(yacc[4], xv, splat2(c1.x));
                    fma2(yacc[5], xv, splat2(c1.y));
                    fma2(yacc[6], xv, splat2(c1.z));
                    fma2(yacc[7], xv, splat2(c1.w));
                    fma2(yacc[8], xv, splat2(c2.x));
                    fma2(yacc[9], xv, splat2(c2.y));
                }
            }
            __syncthreads();
        }

        // flush yacc -> yp, reduce into y
        if (t < 600) {
            #pragma unroll
            for (int i = 0; i < NC; ++i)
                *reinterpret_cast<u64*>(yp_s + jg * (NC * DD) + i * DD + d0c) = yacc[i];
        }
        __syncthreads();
        for (int idx = t; idx < NC * DD; idx += NT)
            y_s[idx] = (yp_s[idx] + yp_s[NC * DD + idx])
                     + (yp_s[2 * NC * DD + idx] + yp_s[3 * NC * DD + idx]);
        __syncthreads();
    }
}

extern "C" void kernel_launch(void* const* d_in, const int* in_sizes, int n_in,
                              void* d_out, int out_size)
{
    const float* x = (const float*)d_in[0];
    const float* W = (const float*)d_in[1];
    if (n_in >= 2 && in_sizes[0] < in_sizes[1]) {
        x = (const float*)d_in[1];
        W = (const float*)d_in[0];
    }
    float* out = (float*)d_out;

    dim3 tb(32, 8);
    dim3 tg(MM / 32, (DD + 31) / 32);
    transpose_W<<<tg, tb>>>(W);

    cudaFuncSetAttribute(caps_kernel, cudaFuncAttributeMaxDynamicSharedMemorySize, SMEM_BYTES);
    caps_kernel<<<BB, NT, SMEM_BYTES>>>(x, W, out);
}